// round 3
// baseline (speedup 1.0000x reference)
#include <cuda_runtime.h>

#define TT 512
#define BTILE 16
#define NTHREADS 256

typedef unsigned long long ull;

// h rows: 16 dup'd ull per k (8 pairs of 16B), pair index XOR-swizzled by (k&7).
#define HROW 16

struct Smem {
    float w0[64 * 256];    // [k][j*4+gate] <- w_hh0[(gate*64+j)*64+k]
    float wi1[64 * 256];   // same regroup of w_ih1
    float wh1[64 * 256];   // same regroup of w_hh1
    ull hA[2][64 * HROW];  // layer-0 hidden, dup'd (h,h), swizzled pairs
    ull hB[2][64 * HROW];  // layer-1 hidden
    float xs[2][BTILE * 4];
};

__device__ __forceinline__ ull pack2(float x, float y) {
    ull r;
    asm("mov.b64 %0, {%1, %2};" : "=l"(r) : "f"(x), "f"(y));
    return r;
}
__device__ __forceinline__ void unpack2(ull v, float& x, float& y) {
    asm("mov.b64 {%0, %1}, %2;" : "=f"(x), "=f"(y) : "l"(v));
}
__device__ __forceinline__ ull fma2(ull a, ull b, ull c) {
    ull d;
    asm("fma.rn.f32x2 %0, %1, %2, %3;" : "=l"(d) : "l"(a), "l"(b), "l"(c));
    return d;
}
__device__ __forceinline__ float tanh_ap(float x) {
    float y;
    asm("tanh.approx.f32 %0, %1;" : "=f"(y) : "f"(x));
    return y;
}
__device__ __forceinline__ float sig_ap(float x) {
    return fmaf(tanh_ap(x * 0.5f), 0.5f, 0.5f);
}

// activations + cell update; h written dup'd+swizzled, c stays in regs
__device__ __forceinline__ void cell_update(const ull aIF[8], const ull aGO[8],
                                            float c[8], ull* __restrict__ dstRow,
                                            int bh4, int jsw) {
    ull hnd[8];
#pragma unroll
    for (int b = 0; b < 8; b++) {
        float gi, gf, gg, go;
        unpack2(aIF[b], gi, gf);
        unpack2(aGO[b], gg, go);
        float I = sig_ap(gi), F = sig_ap(gf), G = tanh_ap(gg), O = sig_ap(go);
        c[b] = F * c[b] + I * G;
        float hh = O * tanh_ap(c[b]);
        hnd[b] = pack2(hh, hh);
    }
#pragma unroll
    for (int p = 0; p < 4; p++) {
        ulonglong2 v;
        v.x = hnd[2 * p];
        v.y = hnd[2 * p + 1];
        *(ulonglong2*)(dstRow + (((bh4 + p) ^ jsw) << 1)) = v;
    }
}

__global__ void __launch_bounds__(NTHREADS, 1)
lstm_fused_kernel(const float* __restrict__ x,
                  const float* __restrict__ w_ih0, const float* __restrict__ w_hh0,
                  const float* __restrict__ b_ih0, const float* __restrict__ b_hh0,
                  const float* __restrict__ w_ih1, const float* __restrict__ w_hh1,
                  const float* __restrict__ b_ih1, const float* __restrict__ b_hh1,
                  const float* __restrict__ fc_w, const float* __restrict__ fc_b,
                  float* __restrict__ out)
{
    extern __shared__ __align__(16) unsigned char smem_raw[];
    Smem& sh = *reinterpret_cast<Smem*>(smem_raw);
    const int tid = threadIdx.x;
    const int b0 = blockIdx.x * BTILE;

    // ---- stage recurrent weights, regrouped: [k][j*4+gate] ----
    for (int e = tid; e < 64 * 256; e += NTHREADS) {
        int row = e >> 6, k = e & 63;
        int gate = row >> 6, jj = row & 63;
        int d = k * 256 + jj * 4 + gate;
        sh.w0[d] = w_hh0[e];
        sh.wi1[d] = w_ih1[e];
        sh.wh1[d] = w_hh1[e];
    }
    // ---- zero h buffers ----
    for (int e = tid; e < 64 * HROW; e += NTHREADS) {
        sh.hA[0][e] = 0ull; sh.hA[1][e] = 0ull;
        sh.hB[0][e] = 0ull; sh.hB[1][e] = 0ull;
    }
    // ---- preload x for t=0 ----
    if (tid < BTILE)
        *(float4*)&sh.xs[0][tid * 4] = ((const float4*)x)[(size_t)(b0 + tid) * TT];

    const bool isG0 = (tid < 128);
    const int local = isG0 ? tid : tid - 128;
    const int j = local & 63;
    const int bh = local >> 6;
    const int bh4 = bh * 4;
    const int jsw = j & 7;

    float wi0[16], bias[4];
    ull biasIF = 0, biasGO = 0;
    if (isG0) {
#pragma unroll
        for (int g = 0; g < 4; g++) {
            float4 wv = *(const float4*)(w_ih0 + (g * 64 + j) * 4);
            wi0[g * 4 + 0] = wv.x; wi0[g * 4 + 1] = wv.y;
            wi0[g * 4 + 2] = wv.z; wi0[g * 4 + 3] = wv.w;
            bias[g] = b_ih0[g * 64 + j] + b_hh0[g * 64 + j];
        }
    } else {
        float bb[4];
#pragma unroll
        for (int g = 0; g < 4; g++) bb[g] = b_ih1[g * 64 + j] + b_hh1[g * 64 + j];
        biasIF = pack2(bb[0], bb[1]);
        biasGO = pack2(bb[2], bb[3]);
    }
    float c[8];
#pragma unroll
    for (int i = 0; i < 8; i++) c[i] = 0.f;

    __syncthreads();

    // ============ pipelined recurrence ============
    // round r: G0 computes layer-0 step t=r (r<512); G1 computes layer-1 step t=r-1 (r>=1)
    for (int r = 0; r <= TT; r++) {
        float4 xpre;
        const bool pre = (tid < BTILE) && (r <= TT - 2);
        if (pre) xpre = ((const float4*)x)[(size_t)(b0 + tid) * TT + (r + 1)];

        if (isG0) {
            if (r < TT) {
                const ull* hr = sh.hA[r & 1];
                const float* wp = sh.w0 + j * 4;
                const float4* xp = (const float4*)sh.xs[r & 1];
                ull aIF[8], aGO[8];
#pragma unroll
                for (int b = 0; b < 8; b++) {
                    float4 xv = xp[bh * 8 + b];
                    float si = bias[0] + wi0[0]*xv.x + wi0[1]*xv.y + wi0[2]*xv.z + wi0[3]*xv.w;
                    float sf = bias[1] + wi0[4]*xv.x + wi0[5]*xv.y + wi0[6]*xv.z + wi0[7]*xv.w;
                    float sg = bias[2] + wi0[8]*xv.x + wi0[9]*xv.y + wi0[10]*xv.z + wi0[11]*xv.w;
                    float so = bias[3] + wi0[12]*xv.x + wi0[13]*xv.y + wi0[14]*xv.z + wi0[15]*xv.w;
                    aIF[b] = pack2(si, sf);
                    aGO[b] = pack2(sg, so);
                }
#pragma unroll 8
                for (int k = 0; k < 64; k++) {
                    const ull* row = hr + k * HROW;
                    const int ks = k & 7;
                    ulonglong2 h0 = *(const ulonglong2*)(row + (((bh4 + 0) ^ ks) << 1));
                    ulonglong2 h1 = *(const ulonglong2*)(row + (((bh4 + 1) ^ ks) << 1));
                    ulonglong2 h2 = *(const ulonglong2*)(row + (((bh4 + 2) ^ ks) << 1));
                    ulonglong2 h3 = *(const ulonglong2*)(row + (((bh4 + 3) ^ ks) << 1));
                    ulonglong2 wv = *(const ulonglong2*)(wp + (k << 8));
                    aIF[0] = fma2(h0.x, wv.x, aIF[0]); aGO[0] = fma2(h0.x, wv.y, aGO[0]);
                    aIF[1] = fma2(h0.y, wv.x, aIF[1]); aGO[1] = fma2(h0.y, wv.y, aGO[1]);
                    aIF[2] = fma2(h1.x, wv.x, aIF[2]); aGO[2] = fma2(h1.x, wv.y, aGO[2]);
                    aIF[3] = fma2(h1.y, wv.x, aIF[3]); aGO[3] = fma2(h1.y, wv.y, aGO[3]);
                    aIF[4] = fma2(h2.x, wv.x, aIF[4]); aGO[4] = fma2(h2.x, wv.y, aGO[4]);
                    aIF[5] = fma2(h2.y, wv.x, aIF[5]); aGO[5] = fma2(h2.y, wv.y, aGO[5]);
                    aIF[6] = fma2(h3.x, wv.x, aIF[6]); aGO[6] = fma2(h3.x, wv.y, aGO[6]);
                    aIF[7] = fma2(h3.y, wv.x, aIF[7]); aGO[7] = fma2(h3.y, wv.y, aGO[7]);
                }
                cell_update(aIF, aGO, c, sh.hA[(r + 1) & 1] + j * HROW, bh4, jsw);
            }
        } else {
            if (r >= 1) {
                const ull* ia = sh.hA[r & 1]; // layer-0 output h0_{r-1}
                const ull* ib = sh.hB[r & 1]; // own state h1_{r-2}
                const float* wip = sh.wi1 + j * 4;
                const float* whp = sh.wh1 + j * 4;
                ull aIF[8], aGO[8];
#pragma unroll
                for (int b = 0; b < 8; b++) { aIF[b] = biasIF; aGO[b] = biasGO; }
#pragma unroll 4
                for (int k = 0; k < 64; k++) {
                    const int ks = k & 7;
                    const ull* rowa = ia + k * HROW;
                    ulonglong2 a0 = *(const ulonglong2*)(rowa + (((bh4 + 0) ^ ks) << 1));
                    ulonglong2 a1 = *(const ulonglong2*)(rowa + (((bh4 + 1) ^ ks) << 1));
                    ulonglong2 a2 = *(const ulonglong2*)(rowa + (((bh4 + 2) ^ ks) << 1));
                    ulonglong2 a3 = *(const ulonglong2*)(rowa + (((bh4 + 3) ^ ks) << 1));
                    ulonglong2 wv = *(const ulonglong2*)(wip + (k << 8));
                    aIF[0] = fma2(a0.x, wv.x, aIF[0]); aGO[0] = fma2(a0.x, wv.y, aGO[0]);
                    aIF[1] = fma2(a0.y, wv.x, aIF[1]); aGO[1] = fma2(a0.y, wv.y, aGO[1]);
                    aIF[2] = fma2(a1.x, wv.x, aIF[2]); aGO[2] = fma2(a1.x, wv.y, aGO[2]);
                    aIF[3] = fma2(a1.y, wv.x, aIF[3]); aGO[3] = fma2(a1.y, wv.y, aGO[3]);
                    aIF[4] = fma2(a2.x, wv.x, aIF[4]); aGO[4] = fma2(a2.x, wv.y, aGO[4]);
                    aIF[5] = fma2(a2.y, wv.x, aIF[5]); aGO[5] = fma2(a2.y, wv.y, aGO[5]);
                    aIF[6] = fma2(a3.x, wv.x, aIF[6]); aGO[6] = fma2(a3.x, wv.y, aGO[6]);
                    aIF[7] = fma2(a3.y, wv.x, aIF[7]); aGO[7] = fma2(a3.y, wv.y, aGO[7]);

                    const ull* rowb = ib + k * HROW;
                    ulonglong2 y0 = *(const ulonglong2*)(rowb + (((bh4 + 0) ^ ks) << 1));
                    ulonglong2 y1 = *(const ulonglong2*)(rowb + (((bh4 + 1) ^ ks) << 1));
                    ulonglong2 y2 = *(const ulonglong2*)(rowb + (((bh4 + 2) ^ ks) << 1));
                    ulonglong2 y3 = *(const ulonglong2*)(rowb + (((bh4 + 3) ^ ks) << 1));
                    ulonglong2 wh = *(const ulonglong2*)(whp + (k << 8));
                    aIF[0] = fma2(y0.x, wh.x, aIF[0]); aGO[0] = fma2(y0.x, wh.y, aGO[0]);
                    aIF[1] = fma2(y0.y, wh.x, aIF[1]); aGO[1] = fma2(y0.y, wh.y, aGO[1]);
                    aIF[2] = fma2(y1.x, wh.x, aIF[2]); aGO[2] = fma2(y1.x, wh.y, aGO[2]);
                    aIF[3] = fma2(y1.y, wh.x, aIF[3]); aGO[3] = fma2(y1.y, wh.y, aGO[3]);
                    aIF[4] = fma2(y2.x, wh.x, aIF[4]); aGO[4] = fma2(y2.x, wh.y, aGO[4]);
                    aIF[5] = fma2(y2.y, wh.x, aIF[5]); aGO[5] = fma2(y2.y, wh.y, aGO[5]);
                    aIF[6] = fma2(y3.x, wh.x, aIF[6]); aGO[6] = fma2(y3.x, wh.y, aGO[6]);
                    aIF[7] = fma2(y3.y, wh.x, aIF[7]); aGO[7] = fma2(y3.y, wh.y, aGO[7]);
                }
                cell_update(aIF, aGO, c, sh.hB[(r + 1) & 1] + j * HROW, bh4, jsw);
            }
        }

        if (pre) *(float4*)&sh.xs[(r + 1) & 1][tid * 4] = xpre;
        __syncthreads();
    }

    // ============ FC + tanh epilogue ============
    // h_n (layer 1, t=511) sits in hB[(TT+1)&1] = hB[1].
    for (int e = tid; e < 4096; e += NTHREADS) {
        int jj = e >> 6, k = e & 63;
        sh.w0[k * 64 + jj] = fc_w[e]; // transpose: [k][j]
    }
    __syncthreads();

    const int q = tid >> 6;  // quarter: 4 batch rows each
    const int jo = tid & 63;
    const ull* hfin = sh.hB[(TT + 1) & 1];
    float fb = fc_b[jo];
    float acc[4];
#pragma unroll
    for (int m = 0; m < 4; m++) acc[m] = fb;
#pragma unroll 8
    for (int k = 0; k < 64; k++) {
        float w = sh.w0[k * 64 + jo];
        const int ks = k & 7;
#pragma unroll
        for (int m = 0; m < 4; m++) {
            int b = q * 4 + m;
            ull e = hfin[k * HROW + (((b >> 1) ^ ks) << 1) + (b & 1)];
            float hv, dummy;
            unpack2(e, hv, dummy);
            acc[m] += w * hv;
        }
    }
#pragma unroll
    for (int m = 0; m < 4; m++)
        out[(size_t)(b0 + q * 4 + m) * 64 + jo] = tanh_ap(acc[m]);
}

extern "C" void kernel_launch(void* const* d_in, const int* in_sizes, int n_in,
                              void* d_out, int out_size) {
    const float* x     = (const float*)d_in[0];
    const float* w_ih0 = (const float*)d_in[1];
    const float* w_hh0 = (const float*)d_in[2];
    const float* b_ih0 = (const float*)d_in[3];
    const float* b_hh0 = (const float*)d_in[4];
    const float* w_ih1 = (const float*)d_in[5];
    const float* w_hh1 = (const float*)d_in[6];
    const float* b_ih1 = (const float*)d_in[7];
    const float* b_hh1 = (const float*)d_in[8];
    const float* fc_w  = (const float*)d_in[9];
    const float* fc_b  = (const float*)d_in[10];
    float* out = (float*)d_out;

    const int smem = (int)sizeof(Smem);
    cudaFuncSetAttribute(lstm_fused_kernel,
                         cudaFuncAttributeMaxDynamicSharedMemorySize, smem);
    lstm_fused_kernel<<<2048 / BTILE, NTHREADS, smem>>>(
        x, w_ih0, w_hh0, b_ih0, b_hh0,
        w_ih1, w_hh1, b_ih1, b_hh1, fc_w, fc_b, out);
}

// round 5
// speedup vs baseline: 1.1101x; 1.1101x over previous
#include <cuda_runtime.h>

#define TT 512
#define BTILE 16
#define NTHREADS 384

typedef unsigned long long ull;

// h layout: 64 rows (k) of 16 dup'd ull, padded 2 ull every 4 rows.
// All offsets 16B-aligned and compile-time constant in unrolled loops.
#define ROWOFF(k) ((k) * 16 + ((k) >> 2) * 2)
#define HTOT (64 * 16 + 16 * 2)   // 1056 ull per buffer

struct Smem {
    float w0[64 * 256];    // [k][j*4+gate] <- w_hh0[(gate*64+j)*64+k]
    float wi1[64 * 256];   // same regroup of w_ih1
    float wh1[64 * 256];   // same regroup of w_hh1
    ull hA[2][HTOT];       // layer-0 hidden, dup'd (h,h)
    ull hB[2][HTOT];       // layer-1 hidden
    float xs[2][BTILE * 4];
};

__device__ __forceinline__ ull pack2(float x, float y) {
    ull r;
    asm("mov.b64 %0, {%1, %2};" : "=l"(r) : "f"(x), "f"(y));
    return r;
}
__device__ __forceinline__ void unpack2(ull v, float& x, float& y) {
    asm("mov.b64 {%0, %1}, %2;" : "=f"(x), "=f"(y) : "l"(v));
}
__device__ __forceinline__ ull fma2(ull a, ull b, ull c) {
    ull d;
    asm("fma.rn.f32x2 %0, %1, %2, %3;" : "=l"(d) : "l"(a), "l"(b), "l"(c));
    return d;
}
__device__ __forceinline__ float tanh_ap(float x) {
    float y;
    asm("tanh.approx.f32 %0, %1;" : "=f"(y) : "f"(x));
    return y;
}
__device__ __forceinline__ float sig_ap(float x) {
    return fmaf(tanh_ap(x * 0.5f), 0.5f, 0.5f);
}

// one cell: gates (i,f) in aIF lanes, (g,o) in aGO lanes -> new h (dup'd)
__device__ __forceinline__ ull one_cell(ull aIF, ull aGO, float& c) {
    float gi, gf, gg, go;
    unpack2(aIF, gi, gf);
    unpack2(aGO, gg, go);
    float I = sig_ap(gi), F = sig_ap(gf), G = tanh_ap(gg), O = sig_ap(go);
    c = F * c + I * G;
    float hh = O * tanh_ap(c);
    return pack2(hh, hh);
}

__global__ void __launch_bounds__(NTHREADS, 1)
lstm_fused_kernel(const float* __restrict__ x,
                  const float* __restrict__ w_ih0, const float* __restrict__ w_hh0,
                  const float* __restrict__ b_ih0, const float* __restrict__ b_hh0,
                  const float* __restrict__ w_ih1, const float* __restrict__ w_hh1,
                  const float* __restrict__ b_ih1, const float* __restrict__ b_hh1,
                  const float* __restrict__ fc_w, const float* __restrict__ fc_b,
                  float* __restrict__ out)
{
    extern __shared__ __align__(16) unsigned char smem_raw[];
    Smem& sh = *reinterpret_cast<Smem*>(smem_raw);
    const int tid = threadIdx.x;
    const int b0 = blockIdx.x * BTILE;

    // ---- stage recurrent weights, regrouped: [k][j*4+gate] ----
    for (int e = tid; e < 64 * 256; e += NTHREADS) {
        int row = e >> 6, k = e & 63;
        int gate = row >> 6, jj = row & 63;
        int d = k * 256 + jj * 4 + gate;
        sh.w0[d] = w_hh0[e];
        sh.wi1[d] = w_ih1[e];
        sh.wh1[d] = w_hh1[e];
    }
    // ---- zero h buffers ----
    for (int e = tid; e < HTOT; e += NTHREADS) {
        sh.hA[0][e] = 0ull; sh.hA[1][e] = 0ull;
        sh.hB[0][e] = 0ull; sh.hB[1][e] = 0ull;
    }
    // ---- preload x for t=0 ----
    if (tid < BTILE)
        *(float4*)&sh.xs[0][tid * 4] = ((const float4*)x)[(size_t)(b0 + tid) * TT];

    const bool isG0 = (tid < 128);

    // G0: 128 threads. j = tid>>1 (16 j per warp), bh = tid&1 -> rows bh*8..+7
    // G1: 256 threads. j = l>>2 (8 j per warp),  bh = l&3   -> rows bh*4..+3
    int j, bh;
    if (isG0) { j = tid >> 1; bh = tid & 1; }
    else      { int l = tid - 128; j = l >> 2; bh = l & 3; }
    const int bh8 = bh * 8;   // G0 row offset (ull)
    const int bh4 = bh * 4;   // G1 row offset (ull)

    float wi0[16], bias[4];
    ull biasIF = 0, biasGO = 0;
    if (isG0) {
#pragma unroll
        for (int g = 0; g < 4; g++) {
            float4 wv = *(const float4*)(w_ih0 + (g * 64 + j) * 4);
            wi0[g * 4 + 0] = wv.x; wi0[g * 4 + 1] = wv.y;
            wi0[g * 4 + 2] = wv.z; wi0[g * 4 + 3] = wv.w;
            bias[g] = b_ih0[g * 64 + j] + b_hh0[g * 64 + j];
        }
    } else {
        float bb[4];
#pragma unroll
        for (int g = 0; g < 4; g++) bb[g] = b_ih1[g * 64 + j] + b_hh1[g * 64 + j];
        biasIF = pack2(bb[0], bb[1]);
        biasGO = pack2(bb[2], bb[3]);
    }
    float c[8];
#pragma unroll
    for (int i = 0; i < 8; i++) c[i] = 0.f;

    __syncthreads();

    // ============ pipelined recurrence ============
    // round r: G0 computes layer-0 step t=r (r<512); G1 computes layer-1 step t=r-1 (r>=1)
    for (int r = 0; r <= TT; r++) {
        float4 xpre;
        const bool pre = (tid < BTILE) && (r <= TT - 2);
        if (pre) xpre = ((const float4*)x)[(size_t)(b0 + tid) * TT + (r + 1)];

        if (isG0) {
            if (r < TT) {
                const ull* hr = sh.hA[r & 1] + bh8;
                const float* wp = sh.w0 + j * 4;
                const float4* xp = (const float4*)sh.xs[r & 1];
                ull aIF[8], aGO[8];
#pragma unroll
                for (int b = 0; b < 8; b++) {
                    float4 xv = xp[bh8 + b];
                    float si = bias[0] + wi0[0]*xv.x + wi0[1]*xv.y + wi0[2]*xv.z + wi0[3]*xv.w;
                    float sf = bias[1] + wi0[4]*xv.x + wi0[5]*xv.y + wi0[6]*xv.z + wi0[7]*xv.w;
                    float sg = bias[2] + wi0[8]*xv.x + wi0[9]*xv.y + wi0[10]*xv.z + wi0[11]*xv.w;
                    float so = bias[3] + wi0[12]*xv.x + wi0[13]*xv.y + wi0[14]*xv.z + wi0[15]*xv.w;
                    aIF[b] = pack2(si, sf);
                    aGO[b] = pack2(sg, so);
                }
#pragma unroll 8
                for (int k = 0; k < 64; k++) {
                    const ull* row = hr + ROWOFF(k);
                    ulonglong2 h0 = *(const ulonglong2*)(row + 0);
                    ulonglong2 h1 = *(const ulonglong2*)(row + 2);
                    ulonglong2 h2 = *(const ulonglong2*)(row + 4);
                    ulonglong2 h3 = *(const ulonglong2*)(row + 6);
                    ulonglong2 wv = *(const ulonglong2*)(wp + (k << 8));
                    aIF[0] = fma2(h0.x, wv.x, aIF[0]); aGO[0] = fma2(h0.x, wv.y, aGO[0]);
                    aIF[1] = fma2(h0.y, wv.x, aIF[1]); aGO[1] = fma2(h0.y, wv.y, aGO[1]);
                    aIF[2] = fma2(h1.x, wv.x, aIF[2]); aGO[2] = fma2(h1.x, wv.y, aGO[2]);
                    aIF[3] = fma2(h1.y, wv.x, aIF[3]); aGO[3] = fma2(h1.y, wv.y, aGO[3]);
                    aIF[4] = fma2(h2.x, wv.x, aIF[4]); aGO[4] = fma2(h2.x, wv.y, aGO[4]);
                    aIF[5] = fma2(h2.y, wv.x, aIF[5]); aGO[5] = fma2(h2.y, wv.y, aGO[5]);
                    aIF[6] = fma2(h3.x, wv.x, aIF[6]); aGO[6] = fma2(h3.x, wv.y, aGO[6]);
                    aIF[7] = fma2(h3.y, wv.x, aIF[7]); aGO[7] = fma2(h3.y, wv.y, aGO[7]);
                }
                ull* dst = sh.hA[(r + 1) & 1] + ROWOFF(j) + bh8;
                ull hn[8];
#pragma unroll
                for (int b = 0; b < 8; b++) hn[b] = one_cell(aIF[b], aGO[b], c[b]);
#pragma unroll
                for (int p = 0; p < 4; p++) {
                    ulonglong2 v; v.x = hn[2 * p]; v.y = hn[2 * p + 1];
                    *(ulonglong2*)(dst + 2 * p) = v;
                }
            }
        } else {
            if (r >= 1) {
                const ull* ia = sh.hA[r & 1] + bh4; // layer-0 output h0_{r-1}
                const ull* ib = sh.hB[r & 1] + bh4; // own state h1_{r-2}
                const float* wip = sh.wi1 + j * 4;
                const float* whp = sh.wh1 + j * 4;
                ull aIF[4], aGO[4];
#pragma unroll
                for (int b = 0; b < 4; b++) { aIF[b] = biasIF; aGO[b] = biasGO; }
#pragma unroll 8
                for (int k = 0; k < 64; k++) {
                    const ull* rowa = ia + ROWOFF(k);
                    ulonglong2 a0 = *(const ulonglong2*)(rowa + 0);
                    ulonglong2 a1 = *(const ulonglong2*)(rowa + 2);
                    ulonglong2 wv = *(const ulonglong2*)(wip + (k << 8));
                    aIF[0] = fma2(a0.x, wv.x, aIF[0]); aGO[0] = fma2(a0.x, wv.y, aGO[0]);
                    aIF[1] = fma2(a0.y, wv.x, aIF[1]); aGO[1] = fma2(a0.y, wv.y, aGO[1]);
                    aIF[2] = fma2(a1.x, wv.x, aIF[2]); aGO[2] = fma2(a1.x, wv.y, aGO[2]);
                    aIF[3] = fma2(a1.y, wv.x, aIF[3]); aGO[3] = fma2(a1.y, wv.y, aGO[3]);

                    const ull* rowb = ib + ROWOFF(k);
                    ulonglong2 y0 = *(const ulonglong2*)(rowb + 0);
                    ulonglong2 y1 = *(const ulonglong2*)(rowb + 2);
                    ulonglong2 wh = *(const ulonglong2*)(whp + (k << 8));
                    aIF[0] = fma2(y0.x, wh.x, aIF[0]); aGO[0] = fma2(y0.x, wh.y, aGO[0]);
                    aIF[1] = fma2(y0.y, wh.x, aIF[1]); aGO[1] = fma2(y0.y, wh.y, aGO[1]);
                    aIF[2] = fma2(y1.x, wh.x, aIF[2]); aGO[2] = fma2(y1.x, wh.y, aGO[2]);
                    aIF[3] = fma2(y1.y, wh.x, aIF[3]); aGO[3] = fma2(y1.y, wh.y, aGO[3]);
                }
                ull* dst = sh.hB[(r + 1) & 1] + ROWOFF(j) + bh4;
                ull hn[4];
#pragma unroll
                for (int b = 0; b < 4; b++) hn[b] = one_cell(aIF[b], aGO[b], c[b]);
#pragma unroll
                for (int p = 0; p < 2; p++) {
                    ulonglong2 v; v.x = hn[2 * p]; v.y = hn[2 * p + 1];
                    *(ulonglong2*)(dst + 2 * p) = v;
                }
            }
        }

        if (pre) *(float4*)&sh.xs[(r + 1) & 1][tid * 4] = xpre;
        __syncthreads();
    }

    // ============ FC + tanh epilogue ============
    // h_n (layer 1, t=511) sits in hB[1], element (k,b) at ull [ROWOFF(k) + b] (dup'd).
    for (int e = tid; e < 4096; e += NTHREADS) {
        int jj = e >> 6, k = e & 63;
        sh.w0[k * 64 + jj] = fc_w[e]; // transpose: [k][j]
    }
    __syncthreads();

    if (tid < 256) {
        const int q = tid >> 6;  // 4 batch rows each
        const int jo = tid & 63;
        const float* hfin = (const float*)sh.hB[1];
        float fb = fc_b[jo];
        float acc[4];
#pragma unroll
        for (int m = 0; m < 4; m++) acc[m] = fb;
#pragma unroll 8
        for (int k = 0; k < 64; k++) {
            float w = sh.w0[k * 64 + jo];
#pragma unroll
            for (int m = 0; m < 4; m++)
                acc[m] += w * hfin[(ROWOFF(k) + q * 4 + m) * 2];
        }
#pragma unroll
        for (int m = 0; m < 4; m++)
            out[(size_t)(b0 + q * 4 + m) * 64 + jo] = tanh_ap(acc[m]);
    }
}

extern "C" void kernel_launch(void* const* d_in, const int* in_sizes, int n_in,
                              void* d_out, int out_size) {
    const float* x     = (const float*)d_in[0];
    const float* w_ih0 = (const float*)d_in[1];
    const float* w_hh0 = (const float*)d_in[2];
    const float* b_ih0 = (const float*)d_in[3];
    const float* b_hh0 = (const float*)d_in[4];
    const float* w_ih1 = (const float*)d_in[5];
    const float* w_hh1 = (const float*)d_in[6];
    const float* b_ih1 = (const float*)d_in[7];
    const float* b_hh1 = (const float*)d_in[8];
    const float* fc_w  = (const float*)d_in[9];
    const float* fc_b  = (const float*)d_in[10];
    float* out = (float*)d_out;

    const int smem = (int)sizeof(Smem);
    cudaFuncSetAttribute(lstm_fused_kernel,
                         cudaFuncAttributeMaxDynamicSharedMemorySize, smem);
    lstm_fused_kernel<<<2048 / BTILE, NTHREADS, smem>>>(
        x, w_ih0, w_hh0, b_ih0, b_hh0,
        w_ih1, w_hh1, b_ih1, b_hh1, fc_w, fc_b, out);
}

// round 6
// speedup vs baseline: 1.1164x; 1.0057x over previous
#include <cuda_runtime.h>

#define TT 512
#define BTILE 16
#define NTHREADS 384

typedef unsigned long long ull;

struct Smem {
    float w0[64 * 256];    // [k][j*4+gate] <- w_hh0[(gate*64+j)*64+k]
    float wi1[64 * 256];   // same regroup of w_ih1
    float wh1[64 * 256];   // same regroup of w_hh1
    float hA[2][64 * 16];  // layer-0 hidden, [buf][k*16 + b], non-dup
    float hB[2][64 * 16];  // layer-1 hidden
    ull   P[16 * 128];     // Gb->Gc partial gates: [i][slot]
    float xs[2][BTILE * 4];
};

__device__ __forceinline__ ull pack2(float x, float y) {
    ull r;
    asm("mov.b64 %0, {%1, %2};" : "=l"(r) : "f"(x), "f"(y));
    return r;
}
__device__ __forceinline__ void unpack2(ull v, float& x, float& y) {
    asm("mov.b64 {%0, %1}, %2;" : "=f"(x), "=f"(y) : "l"(v));
}
__device__ __forceinline__ ull fma2(ull a, ull b, ull c) {
    ull d;
    asm("fma.rn.f32x2 %0, %1, %2, %3;" : "=l"(d) : "l"(a), "l"(b), "l"(c));
    return d;
}
__device__ __forceinline__ ull add2(ull a, ull b) {
    ull d;
    asm("add.rn.f32x2 %0, %1, %2;" : "=l"(d) : "l"(a), "l"(b));
    return d;
}
__device__ __forceinline__ float tanh_ap(float x) {
    float y;
    asm("tanh.approx.f32 %0, %1;" : "=f"(y) : "f"(x));
    return y;
}
__device__ __forceinline__ float sig_ap(float x) {
    return fmaf(tanh_ap(x * 0.5f), 0.5f, 0.5f);
}

// acc[g*4+p] holds gate g for batch rows (2p, 2p+1). Produces 8 h values, c in regs.
__device__ __forceinline__ void cell8(const ull acc[16], float c[8], float hn[8]) {
#pragma unroll
    for (int p = 0; p < 4; p++) {
        float i0, i1, f0, f1, g0, g1, o0, o1;
        unpack2(acc[0 * 4 + p], i0, i1);
        unpack2(acc[1 * 4 + p], f0, f1);
        unpack2(acc[2 * 4 + p], g0, g1);
        unpack2(acc[3 * 4 + p], o0, o1);
        float I0 = sig_ap(i0), F0 = sig_ap(f0), G0 = tanh_ap(g0), O0 = sig_ap(o0);
        c[2 * p] = F0 * c[2 * p] + I0 * G0;
        hn[2 * p] = O0 * tanh_ap(c[2 * p]);
        float I1 = sig_ap(i1), F1 = sig_ap(f1), G1 = tanh_ap(g1), O1 = sig_ap(o1);
        c[2 * p + 1] = F1 * c[2 * p + 1] + I1 * G1;
        hn[2 * p + 1] = O1 * tanh_ap(c[2 * p + 1]);
    }
}

// one K=64 matvec accumulation: h warp-uniform pairs, w contiguous float4 + dup packs
__device__ __forceinline__ void matvec64(const float* __restrict__ hr,
                                         const float* __restrict__ wp,
                                         ull acc[16]) {
#pragma unroll 8
    for (int k = 0; k < 64; k++) {
        ulonglong2 hp0 = *(const ulonglong2*)(hr + k * 16);      // rows b0..b3
        ulonglong2 hp1 = *(const ulonglong2*)(hr + k * 16 + 4);  // rows b4..b7
        float4 w = *(const float4*)(wp + (k << 8));
        ull wI = pack2(w.x, w.x), wF = pack2(w.y, w.y);
        ull wG = pack2(w.z, w.z), wO = pack2(w.w, w.w);
        acc[0]  = fma2(hp0.x, wI, acc[0]);  acc[1]  = fma2(hp0.y, wI, acc[1]);
        acc[2]  = fma2(hp1.x, wI, acc[2]);  acc[3]  = fma2(hp1.y, wI, acc[3]);
        acc[4]  = fma2(hp0.x, wF, acc[4]);  acc[5]  = fma2(hp0.y, wF, acc[5]);
        acc[6]  = fma2(hp1.x, wF, acc[6]);  acc[7]  = fma2(hp1.y, wF, acc[7]);
        acc[8]  = fma2(hp0.x, wG, acc[8]);  acc[9]  = fma2(hp0.y, wG, acc[9]);
        acc[10] = fma2(hp1.x, wG, acc[10]); acc[11] = fma2(hp1.y, wG, acc[11]);
        acc[12] = fma2(hp0.x, wO, acc[12]); acc[13] = fma2(hp0.y, wO, acc[13]);
        acc[14] = fma2(hp1.x, wO, acc[14]); acc[15] = fma2(hp1.y, wO, acc[15]);
    }
}

__global__ void __launch_bounds__(NTHREADS, 1)
lstm_fused_kernel(const float* __restrict__ x,
                  const float* __restrict__ w_ih0, const float* __restrict__ w_hh0,
                  const float* __restrict__ b_ih0, const float* __restrict__ b_hh0,
                  const float* __restrict__ w_ih1, const float* __restrict__ w_hh1,
                  const float* __restrict__ b_ih1, const float* __restrict__ b_hh1,
                  const float* __restrict__ fc_w, const float* __restrict__ fc_b,
                  float* __restrict__ out)
{
    extern __shared__ __align__(16) unsigned char smem_raw[];
    Smem& sh = *reinterpret_cast<Smem*>(smem_raw);
    const int tid = threadIdx.x;
    const int b0 = blockIdx.x * BTILE;

    // ---- stage recurrent weights, regrouped: [k][j*4+gate] ----
    for (int e = tid; e < 64 * 256; e += NTHREADS) {
        int row = e >> 6, k = e & 63;
        int gate = row >> 6, jj = row & 63;
        int d = k * 256 + jj * 4 + gate;
        sh.w0[d] = w_hh0[e];
        sh.wi1[d] = w_ih1[e];
        sh.wh1[d] = w_hh1[e];
    }
    // ---- zero h buffers ----
    for (int e = tid; e < 1024; e += NTHREADS) {
        sh.hA[0][e] = 0.f; sh.hA[1][e] = 0.f;
        sh.hB[0][e] = 0.f; sh.hB[1][e] = 0.f;
    }
    // ---- preload x for t=0 (Gb lanes) ----
    if (tid >= 128 && tid < 128 + BTILE) {
        int b = tid - 128;
        *(float4*)&sh.xs[0][b * 4] = ((const float4*)x)[(size_t)(b0 + b) * TT];
    }

    const int wid = tid >> 5;
    const int lane = tid & 31;
    const int grp = wid >> 2;      // 0=Ga, 1=Gb, 2=Gc
    const int lw = wid & 3;        // warp within group
    const int bh = lw & 1;         // batch half
    const int j = lane + ((lw >> 1) << 5); // hidden unit 0..63
    const int bh8 = bh * 8;
    const int slot = lw * 32 + lane;       // P slot 0..127 (same for Gb/Gc pair)

    float wi0[16], bias0[4];
    ull biasIF[4] = {0, 0, 0, 0};   // Gb: per-gate dup'd bias (i,f,g,o)
    if (grp == 0) {
#pragma unroll
        for (int g = 0; g < 4; g++) {
            float4 wv = *(const float4*)(w_ih0 + (g * 64 + j) * 4);
            wi0[g * 4 + 0] = wv.x; wi0[g * 4 + 1] = wv.y;
            wi0[g * 4 + 2] = wv.z; wi0[g * 4 + 3] = wv.w;
            bias0[g] = b_ih0[g * 64 + j] + b_hh0[g * 64 + j];
        }
    } else if (grp == 1) {
#pragma unroll
        for (int g = 0; g < 4; g++) {
            float bb = b_ih1[g * 64 + j] + b_hh1[g * 64 + j];
            biasIF[g] = pack2(bb, bb);
        }
    }
    float c[8];
#pragma unroll
    for (int i = 0; i < 8; i++) c[i] = 0.f;

    __syncthreads();

    // ============ pipelined recurrence ============
    // round r: Ga: layer-0 t=r (r<512); Gb: W_ih1*h0[r-1]; Gc: W_hh1*h1[r-2] + finish h1[r-1]
    for (int r = 0; r <= TT; r++) {
        float4 xpre;
        const bool pre = (tid >= 128) && (tid < 128 + BTILE) && (r <= TT - 2);
        if (pre) xpre = ((const float4*)x)[(size_t)(b0 + (tid - 128)) * TT + (r + 1)];

        if (grp == 0) {
            if (r < TT) {
                ull acc[16];
                const float4* xp = (const float4*)sh.xs[r & 1];
#pragma unroll
                for (int p = 0; p < 4; p++) {
                    float4 xa = xp[bh8 + 2 * p];
                    float4 xb = xp[bh8 + 2 * p + 1];
#pragma unroll
                    for (int g = 0; g < 4; g++) {
                        float s0 = bias0[g] + wi0[g*4]*xa.x + wi0[g*4+1]*xa.y
                                            + wi0[g*4+2]*xa.z + wi0[g*4+3]*xa.w;
                        float s1 = bias0[g] + wi0[g*4]*xb.x + wi0[g*4+1]*xb.y
                                            + wi0[g*4+2]*xb.z + wi0[g*4+3]*xb.w;
                        acc[g * 4 + p] = pack2(s0, s1);
                    }
                }
                matvec64(sh.hA[r & 1] + bh8, sh.w0 + j * 4, acc);
                float hn[8];
                cell8(acc, c, hn);
                float* dst = sh.hA[(r + 1) & 1] + j * 16 + bh8;
                *(float4*)dst = make_float4(hn[0], hn[1], hn[2], hn[3]);
                *(float4*)(dst + 4) = make_float4(hn[4], hn[5], hn[6], hn[7]);
            }
        } else if (grp == 1) {
            if (r >= 1) {
                ull acc[16];
#pragma unroll
                for (int g = 0; g < 4; g++)
#pragma unroll
                    for (int p = 0; p < 4; p++) acc[g * 4 + p] = biasIF[g];
                matvec64(sh.hA[r & 1] + bh8, sh.wi1 + j * 4, acc);
                // publish partial: P[i][slot]
#pragma unroll
                for (int i = 0; i < 16; i++) sh.P[i * 128 + slot] = acc[i];
                asm volatile("bar.sync %0, 64;" :: "r"(1 + lw) : "memory");
            }
        } else {
            if (r >= 1) {
                ull acc[16];
#pragma unroll
                for (int i = 0; i < 16; i++) acc[i] = 0ull;
                matvec64(sh.hB[r & 1] + bh8, sh.wh1 + j * 4, acc);
                asm volatile("bar.sync %0, 64;" :: "r"(1 + lw) : "memory");
#pragma unroll
                for (int i = 0; i < 16; i++) acc[i] = add2(acc[i], sh.P[i * 128 + slot]);
                float hn[8];
                cell8(acc, c, hn);
                float* dst = sh.hB[(r + 1) & 1] + j * 16 + bh8;
                *(float4*)dst = make_float4(hn[0], hn[1], hn[2], hn[3]);
                *(float4*)(dst + 4) = make_float4(hn[4], hn[5], hn[6], hn[7]);
            }
        }

        if (pre) *(float4*)&sh.xs[(r + 1) & 1][(tid - 128) * 4] = xpre;
        __syncthreads();
    }

    // ============ FC + tanh epilogue ============
    // h_n (layer 1, t=511) finalized in round 512 -> hB[(512+1)&1] = hB[1].
    for (int e = tid; e < 4096; e += NTHREADS) {
        int jj = e >> 6, k = e & 63;
        sh.w0[k * 64 + jj] = fc_w[e]; // transpose: [k][j]
    }
    __syncthreads();

    if (tid < 256) {
        const int q = tid >> 6;  // 4 batch rows each
        const int jo = tid & 63;
        const float* hfin = sh.hB[1];
        float fb = fc_b[jo];
        float acc[4];
#pragma unroll
        for (int m = 0; m < 4; m++) acc[m] = fb;
#pragma unroll 8
        for (int k = 0; k < 64; k++) {
            float w = sh.w0[k * 64 + jo];
#pragma unroll
            for (int m = 0; m < 4; m++)
                acc[m] += w * hfin[k * 16 + q * 4 + m];
        }
#pragma unroll
        for (int m = 0; m < 4; m++)
            out[(size_t)(b0 + q * 4 + m) * 64 + jo] = tanh_ap(acc[m]);
    }
}

extern "C" void kernel_launch(void* const* d_in, const int* in_sizes, int n_in,
                              void* d_out, int out_size) {
    const float* x     = (const float*)d_in[0];
    const float* w_ih0 = (const float*)d_in[1];
    const float* w_hh0 = (const float*)d_in[2];
    const float* b_ih0 = (const float*)d_in[3];
    const float* b_hh0 = (const float*)d_in[4];
    const float* w_ih1 = (const float*)d_in[5];
    const float* w_hh1 = (const float*)d_in[6];
    const float* b_ih1 = (const float*)d_in[7];
    const float* b_hh1 = (const float*)d_in[8];
    const float* fc_w  = (const float*)d_in[9];
    const float* fc_b  = (const float*)d_in[10];
    float* out = (float*)d_out;

    const int smem = (int)sizeof(Smem);
    cudaFuncSetAttribute(lstm_fused_kernel,
                         cudaFuncAttributeMaxDynamicSharedMemorySize, smem);
    lstm_fused_kernel<<<2048 / BTILE, NTHREADS, smem>>>(
        x, w_ih0, w_hh0, b_ih0, b_hh0,
        w_ih1, w_hh1, b_ih1, b_hh1, fc_w, fc_b, out);
}

// round 7
// speedup vs baseline: 1.4572x; 1.3053x over previous
#include <cuda_runtime.h>

#define TT 512
#define BTILE 16
#define NTHREADS 768

typedef unsigned long long ull;

struct Smem {
    float w0[64 * 256];    // [k][j*4+gate] <- w_hh0[(gate*64+j)*64+k]
    float wi1[64 * 256];   // same regroup of w_ih1
    float wh1[64 * 256];   // same regroup of w_hh1
    float hA[2][64 * 16];  // layer-0 hidden, [buf][k*16 + b]
    float hB[2][64 * 16];  // layer-1 hidden
    ull   P[8 * 256];      // Gb->Gc partial gates: [i][slot]
    float xs[2][BTILE * 4];
};

__device__ __forceinline__ ull pack2(float x, float y) {
    ull r;
    asm("mov.b64 %0, {%1, %2};" : "=l"(r) : "f"(x), "f"(y));
    return r;
}
__device__ __forceinline__ void unpack2(ull v, float& x, float& y) {
    asm("mov.b64 {%0, %1}, %2;" : "=f"(x), "=f"(y) : "l"(v));
}
__device__ __forceinline__ ull fma2(ull a, ull b, ull c) {
    ull d;
    asm("fma.rn.f32x2 %0, %1, %2, %3;" : "=l"(d) : "l"(a), "l"(b), "l"(c));
    return d;
}
__device__ __forceinline__ ull add2(ull a, ull b) {
    ull d;
    asm("add.rn.f32x2 %0, %1, %2;" : "=l"(d) : "l"(a), "l"(b));
    return d;
}
__device__ __forceinline__ float tanh_ap(float x) {
    float y;
    asm("tanh.approx.f32 %0, %1;" : "=f"(y) : "f"(x));
    return y;
}
__device__ __forceinline__ float sig_ap(float x) {
    return fmaf(tanh_ap(x * 0.5f), 0.5f, 0.5f);
}

// acc[g*2+p]: gate g, batch row-pair p (rows 2p,2p+1 of this thread's quad)
__device__ __forceinline__ void cell4(const ull acc[8], float c[4], float hn[4]) {
#pragma unroll
    for (int p = 0; p < 2; p++) {
        float i0, i1, f0, f1, g0, g1, o0, o1;
        unpack2(acc[0 * 2 + p], i0, i1);
        unpack2(acc[1 * 2 + p], f0, f1);
        unpack2(acc[2 * 2 + p], g0, g1);
        unpack2(acc[3 * 2 + p], o0, o1);
        float I0 = sig_ap(i0), F0 = sig_ap(f0), G0 = tanh_ap(g0), O0 = sig_ap(o0);
        c[2 * p] = F0 * c[2 * p] + I0 * G0;
        hn[2 * p] = O0 * tanh_ap(c[2 * p]);
        float I1 = sig_ap(i1), F1 = sig_ap(f1), G1 = tanh_ap(g1), O1 = sig_ap(o1);
        c[2 * p + 1] = F1 * c[2 * p + 1] + I1 * G1;
        hn[2 * p + 1] = O1 * tanh_ap(c[2 * p + 1]);
    }
}

// K=64 matvec: h = 16B/lane (4 lanes cover 64B row run -> 1 wf),
// w = float4 shared by 4 lanes (broadcast -> 1 wf).
__device__ __forceinline__ void matvec64(const float* __restrict__ hr,
                                         const float* __restrict__ wp,
                                         ull acc[8]) {
#pragma unroll 8
    for (int k = 0; k < 64; k++) {
        ulonglong2 hp = *(const ulonglong2*)(hr + k * 16);
        float4 w = *(const float4*)(wp + (k << 8));
        ull wI = pack2(w.x, w.x), wF = pack2(w.y, w.y);
        ull wG = pack2(w.z, w.z), wO = pack2(w.w, w.w);
        acc[0] = fma2(hp.x, wI, acc[0]); acc[1] = fma2(hp.y, wI, acc[1]);
        acc[2] = fma2(hp.x, wF, acc[2]); acc[3] = fma2(hp.y, wF, acc[3]);
        acc[4] = fma2(hp.x, wG, acc[4]); acc[5] = fma2(hp.y, wG, acc[5]);
        acc[6] = fma2(hp.x, wO, acc[6]); acc[7] = fma2(hp.y, wO, acc[7]);
    }
}

__global__ void __launch_bounds__(NTHREADS, 1)
lstm_fused_kernel(const float* __restrict__ x,
                  const float* __restrict__ w_ih0, const float* __restrict__ w_hh0,
                  const float* __restrict__ b_ih0, const float* __restrict__ b_hh0,
                  const float* __restrict__ w_ih1, const float* __restrict__ w_hh1,
                  const float* __restrict__ b_ih1, const float* __restrict__ b_hh1,
                  const float* __restrict__ fc_w, const float* __restrict__ fc_b,
                  float* __restrict__ out)
{
    extern __shared__ __align__(16) unsigned char smem_raw[];
    Smem& sh = *reinterpret_cast<Smem*>(smem_raw);
    const int tid = threadIdx.x;
    const int b0 = blockIdx.x * BTILE;

    // ---- stage recurrent weights, regrouped: [k][j*4+gate] ----
    for (int e = tid; e < 64 * 256; e += NTHREADS) {
        int row = e >> 6, k = e & 63;
        int gate = row >> 6, jj = row & 63;
        int d = k * 256 + jj * 4 + gate;
        sh.w0[d] = w_hh0[e];
        sh.wi1[d] = w_ih1[e];
        sh.wh1[d] = w_hh1[e];
    }
    // ---- zero h buffers ----
    for (int e = tid; e < 1024; e += NTHREADS) {
        sh.hA[0][e] = 0.f; sh.hA[1][e] = 0.f;
        sh.hB[0][e] = 0.f; sh.hB[1][e] = 0.f;
    }
    // ---- preload x for t=0 ----
    if (tid >= 256 && tid < 256 + BTILE) {
        int b = tid - 256;
        *(float4*)&sh.xs[0][b * 4] = ((const float4*)x)[(size_t)(b0 + b) * TT];
    }

    const int wid = tid >> 5;
    const int lane = tid & 31;
    const int grp = wid >> 3;              // 0=Ga, 1=Gb, 2=Gc
    const int lw = wid & 7;                // warp within group
    const int j = lw * 8 + (lane >> 2);    // hidden unit 0..63
    const int quad = lane & 3;             // batch quad: rows quad*4..+3
    const int q4 = quad * 4;
    const int slot = lw * 32 + lane;       // P slot (same for Gb/Gc pair)

    float wi0[16], bias0[4];
    ull bias1[4] = {0, 0, 0, 0};
    if (grp == 0) {
#pragma unroll
        for (int g = 0; g < 4; g++) {
            float4 wv = *(const float4*)(w_ih0 + (g * 64 + j) * 4);
            wi0[g * 4 + 0] = wv.x; wi0[g * 4 + 1] = wv.y;
            wi0[g * 4 + 2] = wv.z; wi0[g * 4 + 3] = wv.w;
            bias0[g] = b_ih0[g * 64 + j] + b_hh0[g * 64 + j];
        }
    } else if (grp == 1) {
#pragma unroll
        for (int g = 0; g < 4; g++) {
            float bb = b_ih1[g * 64 + j] + b_hh1[g * 64 + j];
            bias1[g] = pack2(bb, bb);
        }
    }
    float c[4];
#pragma unroll
    for (int i = 0; i < 4; i++) c[i] = 0.f;

    __syncthreads();

    // ============ pipelined recurrence ============
    // round r: Ga: layer-0 t=r (r<512); Gb: W_ih1*h0[r-1]; Gc: W_hh1*h1[r-2] + cell -> h1[r-1]
    for (int r = 0; r <= TT; r++) {
        float4 xpre;
        const bool pre = (tid >= 256) && (tid < 256 + BTILE) && (r <= TT - 2);
        if (pre) xpre = ((const float4*)x)[(size_t)(b0 + (tid - 256)) * TT + (r + 1)];

        if (grp == 0) {
            if (r < TT) {
                ull acc[8];
                const float4* xp = (const float4*)sh.xs[r & 1];
#pragma unroll
                for (int p = 0; p < 2; p++) {
                    float4 xa = xp[q4 + 2 * p];
                    float4 xb = xp[q4 + 2 * p + 1];
#pragma unroll
                    for (int g = 0; g < 4; g++) {
                        float s0 = bias0[g] + wi0[g*4]*xa.x + wi0[g*4+1]*xa.y
                                            + wi0[g*4+2]*xa.z + wi0[g*4+3]*xa.w;
                        float s1 = bias0[g] + wi0[g*4]*xb.x + wi0[g*4+1]*xb.y
                                            + wi0[g*4+2]*xb.z + wi0[g*4+3]*xb.w;
                        acc[g * 2 + p] = pack2(s0, s1);
                    }
                }
                matvec64(sh.hA[r & 1] + q4, sh.w0 + j * 4, acc);
                float hn[4];
                cell4(acc, c, hn);
                *(float4*)(sh.hA[(r + 1) & 1] + j * 16 + q4) =
                    make_float4(hn[0], hn[1], hn[2], hn[3]);
            }
        } else if (grp == 1) {
            if (r >= 1) {
                ull acc[8];
#pragma unroll
                for (int g = 0; g < 4; g++) {
                    acc[g * 2] = bias1[g];
                    acc[g * 2 + 1] = bias1[g];
                }
                matvec64(sh.hA[r & 1] + q4, sh.wi1 + j * 4, acc);
#pragma unroll
                for (int i = 0; i < 8; i++) sh.P[i * 256 + slot] = acc[i];
                asm volatile("bar.sync %0, 64;" :: "r"(1 + lw) : "memory");
            }
        } else {
            if (r >= 1) {
                ull acc[8];
#pragma unroll
                for (int i = 0; i < 8; i++) acc[i] = 0ull;
                matvec64(sh.hB[r & 1] + q4, sh.wh1 + j * 4, acc);
                asm volatile("bar.sync %0, 64;" :: "r"(1 + lw) : "memory");
#pragma unroll
                for (int i = 0; i < 8; i++) acc[i] = add2(acc[i], sh.P[i * 256 + slot]);
                float hn[4];
                cell4(acc, c, hn);
                *(float4*)(sh.hB[(r + 1) & 1] + j * 16 + q4) =
                    make_float4(hn[0], hn[1], hn[2], hn[3]);
            }
        }

        if (pre) *(float4*)&sh.xs[(r + 1) & 1][(tid - 256) * 4] = xpre;
        __syncthreads();
    }

    // ============ FC + tanh epilogue ============
    // h_n (layer 1, t=511) finalized in round 512 -> hB[1].
    for (int e = tid; e < 4096; e += NTHREADS) {
        int jj = e >> 6, k = e & 63;
        sh.w0[k * 64 + jj] = fc_w[e]; // transpose: [k][j]
    }
    __syncthreads();

    if (tid < 256) {
        const int q = tid >> 6;  // 4 batch rows each
        const int jo = tid & 63;
        const float* hfin = sh.hB[1];
        float fb = fc_b[jo];
        float acc[4];
#pragma unroll
        for (int m = 0; m < 4; m++) acc[m] = fb;
#pragma unroll 8
        for (int k = 0; k < 64; k++) {
            float w = sh.w0[k * 64 + jo];
#pragma unroll
            for (int m = 0; m < 4; m++)
                acc[m] += w * hfin[k * 16 + q * 4 + m];
        }
#pragma unroll
        for (int m = 0; m < 4; m++)
            out[(size_t)(b0 + q * 4 + m) * 64 + jo] = tanh_ap(acc[m]);
    }
}

extern "C" void kernel_launch(void* const* d_in, const int* in_sizes, int n_in,
                              void* d_out, int out_size) {
    const float* x     = (const float*)d_in[0];
    const float* w_ih0 = (const float*)d_in[1];
    const float* w_hh0 = (const float*)d_in[2];
    const float* b_ih0 = (const float*)d_in[3];
    const float* b_hh0 = (const float*)d_in[4];
    const float* w_ih1 = (const float*)d_in[5];
    const float* w_hh1 = (const float*)d_in[6];
    const float* b_ih1 = (const float*)d_in[7];
    const float* b_hh1 = (const float*)d_in[8];
    const float* fc_w  = (const float*)d_in[9];
    const float* fc_b  = (const float*)d_in[10];
    float* out = (float*)d_out;

    const int smem = (int)sizeof(Smem);
    cudaFuncSetAttribute(lstm_fused_kernel,
                         cudaFuncAttributeMaxDynamicSharedMemorySize, smem);
    lstm_fused_kernel<<<2048 / BTILE, NTHREADS, smem>>>(
        x, w_ih0, w_hh0, b_ih0, b_hh0,
        w_ih1, w_hh1, b_ih1, b_hh1, fc_w, fc_b, out);
}